// round 11
// baseline (speedup 1.0000x reference)
#include <cuda_runtime.h>
#include <cuda_bf16.h>

#define NN 2048
#define RR 4
#define NT 256
#define BR3(j) ((((j)&1)<<2) | ((j)&2) | (((j)&4)>>2))

// Filters, storage index fidx = 256v + 32s + c  (frequency k = 256v + 8c + s)
__device__ float2 g_Ghat[RR][NN];
__device__ float2 g_Hhat[RR][NN];
__device__ float2 g_HH[2][NN];
__device__ float2 g_A [2][NN];
__device__ float2 g_B [2][NN];

__device__ __forceinline__ float2 cadd(float2 a, float2 b){ return make_float2(a.x+b.x, a.y+b.y); }
__device__ __forceinline__ float2 csub(float2 a, float2 b){ return make_float2(a.x-b.x, a.y-b.y); }
__device__ __forceinline__ float2 cmul(float2 a, float2 b){
    return make_float2(a.x*b.x - a.y*b.y, a.x*b.y + a.y*b.x);
}
__device__ __forceinline__ float2 cmulj(float2 a, float2 b){   // a * conj(b)
    return make_float2(a.x*b.x + a.y*b.y, a.y*b.x - a.x*b.y);
}
__device__ __forceinline__ float2 csqr(float2 a){ return make_float2(a.x*a.x - a.y*a.y, 2.f*a.x*a.y); }
__device__ __forceinline__ int br5(int x){ return (int)(__brev((unsigned)x) >> 27); }

__device__ __forceinline__ float2 shfl_xor_c(float2 v, int m){
    return make_float2(__shfl_xor_sync(0xffffffffu, v.x, m),
                       __shfl_xor_sync(0xffffffffu, v.y, m));
}
__device__ __forceinline__ float2 bfly(float2 p, float2 v, float s){
    return make_float2(fmaf(s, v.x, p.x), fmaf(s, v.y, p.y));
}

struct LaneTw {
    float2 W16, W8, W4;
    float s16, s8, s4, s2, s1;
};

__device__ __forceinline__ LaneTw make_lane_tw(int lane){
    float s, c;
    sincospif((float)(lane & 15) * (1.f/16.f), &s, &c);
    float2 w16 = make_float2(c, -s);
    float2 w8 = csqr(w16); if (lane & 8){ w8.x = -w8.x; w8.y = -w8.y; }
    float2 w4 = csqr(w8);  if (lane & 4){ w4.x = -w4.x; w4.y = -w4.y; }
    LaneTw T;
    T.W16 = (lane & 16) ? w16 : make_float2(1.f, 0.f);
    T.W8  = (lane & 8)  ? w8  : make_float2(1.f, 0.f);
    T.W4  = (lane & 4)  ? w4  : make_float2(1.f, 0.f);
    T.s16 = (lane & 16) ? -1.f : 1.f;
    T.s8  = (lane & 8)  ? -1.f : 1.f;
    T.s4  = (lane & 4)  ? -1.f : 1.f;
    T.s2  = (lane & 2)  ? -1.f : 1.f;
    T.s1  = (lane & 1)  ? -1.f : 1.f;
    return T;
}

__device__ __forceinline__ float2 fft32_fwd(float2 v, const LaneTw& T, int lane){
    float2 p, t;
    p = shfl_xor_c(v, 16);
    t = bfly(p, v, T.s16);  v = cmul(t, T.W16);
    p = shfl_xor_c(v, 8);
    t = bfly(p, v, T.s8);   v = cmul(t, T.W8);
    p = shfl_xor_c(v, 4);
    t = bfly(p, v, T.s4);   v = cmul(t, T.W4);
    p = shfl_xor_c(v, 2);
    t = bfly(p, v, T.s2);
    v = ((lane & 3) == 3) ? make_float2(t.y, -t.x) : t;
    p = shfl_xor_c(v, 1);
    v = bfly(p, v, T.s1);
    return v;
}

__device__ __forceinline__ float2 fft32_inv(float2 v, const LaneTw& T, int lane){
    float2 p;
    p = shfl_xor_c(v, 1);
    v = bfly(p, v, T.s1);
    if ((lane & 3) == 3) v = make_float2(-v.y, v.x);
    p = shfl_xor_c(v, 2);
    v = bfly(p, v, T.s2);
    v = cmulj(v, T.W4);
    p = shfl_xor_c(v, 4);
    v = bfly(p, v, T.s4);
    v = cmulj(v, T.W8);
    p = shfl_xor_c(v, 8);
    v = bfly(p, v, T.s8);
    v = cmulj(v, T.W16);
    p = shfl_xor_c(v, 16);
    v = bfly(p, v, T.s16);
    return v;
}

__device__ __forceinline__ void fft8_fwd(float2 r[8]){
    const float R2 = 0.70710678118654752440f;
    float2 a, d;
    a = r[0]; r[0] = cadd(a, r[4]); r[4] = csub(a, r[4]);
    a = r[1]; d = csub(a, r[5]); r[1] = cadd(a, r[5]);
              r[5] = make_float2((d.x + d.y)*R2, (d.y - d.x)*R2);
    a = r[2]; d = csub(a, r[6]); r[2] = cadd(a, r[6]);
              r[6] = make_float2(d.y, -d.x);
    a = r[3]; d = csub(a, r[7]); r[3] = cadd(a, r[7]);
              r[7] = make_float2((d.y - d.x)*R2, -(d.x + d.y)*R2);
    a = r[0]; r[0] = cadd(a, r[2]); r[2] = csub(a, r[2]);
    a = r[1]; d = csub(a, r[3]); r[1] = cadd(a, r[3]); r[3] = make_float2(d.y, -d.x);
    a = r[4]; r[4] = cadd(a, r[6]); r[6] = csub(a, r[6]);
    a = r[5]; d = csub(a, r[7]); r[5] = cadd(a, r[7]); r[7] = make_float2(d.y, -d.x);
    a = r[0]; r[0] = cadd(a, r[1]); r[1] = csub(a, r[1]);
    a = r[2]; r[2] = cadd(a, r[3]); r[3] = csub(a, r[3]);
    a = r[4]; r[4] = cadd(a, r[5]); r[5] = csub(a, r[5]);
    a = r[6]; r[6] = cadd(a, r[7]); r[7] = csub(a, r[7]);
}

__device__ __forceinline__ void fft8_inv(float2 r[8]){
    const float R2 = 0.70710678118654752440f;
    float2 a, d;
    a = r[0]; r[0] = cadd(a, r[1]); r[1] = csub(a, r[1]);
    a = r[2]; r[2] = cadd(a, r[3]); r[3] = csub(a, r[3]);
    a = r[4]; r[4] = cadd(a, r[5]); r[5] = csub(a, r[5]);
    a = r[6]; r[6] = cadd(a, r[7]); r[7] = csub(a, r[7]);
    a = r[0]; r[0] = cadd(a, r[2]); r[2] = csub(a, r[2]);
    d = make_float2(-r[3].y, r[3].x); a = r[1]; r[1] = cadd(a, d); r[3] = csub(a, d);
    a = r[4]; r[4] = cadd(a, r[6]); r[6] = csub(a, r[6]);
    d = make_float2(-r[7].y, r[7].x); a = r[5]; r[5] = cadd(a, d); r[7] = csub(a, d);
    d = r[4];                                       a = r[0]; r[0] = cadd(a, d); r[4] = csub(a, d);
    d = make_float2((r[5].x - r[5].y)*R2, (r[5].x + r[5].y)*R2);
                                                    a = r[1]; r[1] = cadd(a, d); r[5] = csub(a, d);
    d = make_float2(-r[6].y, r[6].x);               a = r[2]; r[2] = cadd(a, d); r[6] = csub(a, d);
    d = make_float2(-(r[7].x + r[7].y)*R2, (r[7].x - r[7].y)*R2);
                                                    a = r[3]; r[3] = cadd(a, d); r[7] = csub(a, d);
}

// Forward 2048: xt[t] at n = n0 + 256t (n0 = w + 8*lane) -> xh[v] = X[256v+8*lane+w]
// twb = e^{-i pi n0/1024}; digit twiddles streamed via 2-reg recurrence.
__device__ __forceinline__ void fwd2048(float2 xt[8], float2 xh[8], float2* sm2,
                                        float2 twb, float2 tw2,
                                        const LaneTw& T, int lane, int w)
{
    fft8_fwd(xt);
    {
        float2 cur = twb;
#pragma unroll
        for (int s = 1; s < 8; s++){
            xt[BR3(s)] = cmul(xt[BR3(s)], cur);
            if (s < 7) cur = cmul(cur, twb);
        }
    }
    int c = br5(lane);
    __syncthreads();
#pragma unroll
    for (int j = 0; j < 8; j++){
        float2 v = fft32_fwd(xt[j], T, lane);
        v = cmul(v, tw2);
        sm2[(w*8 + BR3(j))*33 + c] = v;
    }
    __syncthreads();
    float2 m[8];
#pragma unroll
    for (int rr = 0; rr < 8; rr++) m[rr] = sm2[(rr*8 + w)*33 + lane];
    fft8_fwd(m);
#pragma unroll
    for (int v = 0; v < 8; v++) xh[v] = m[BR3(v)];
}

// Inverse (unscaled x2048): q[v] spectrum -> xt[t] time
__device__ __forceinline__ void inv2048(float2 q[8], float2 xt[8], float2* sm2,
                                        float2 twb, float2 tw2,
                                        const LaneTw& T, int lane, int w)
{
    float2 r[8];
#pragma unroll
    for (int j = 0; j < 8; j++) r[j] = q[BR3(j)];
    fft8_inv(r);
    __syncthreads();
#pragma unroll
    for (int rr = 0; rr < 8; rr++) sm2[(rr*8 + w)*33 + lane] = r[rr];
    __syncthreads();
    int c = br5(lane);
    float2 rs[8];
#pragma unroll
    for (int s = 0; s < 8; s++){
        float2 v = sm2[(w*8 + s)*33 + c];
        v = cmulj(v, tw2);
        rs[s] = fft32_inv(v, T, lane);
    }
    xt[0] = rs[0];
    {
        float2 cur = twb;
#pragma unroll
        for (int s = 1; s < 8; s++){
            xt[BR3(s)] = cmulj(rs[s], cur);
            if (s < 7) cur = cmul(cur, twb);
        }
    }
    fft8_inv(xt);
}

__device__ __forceinline__ void setup_tw(float2& twb, float2& tw2, int n0, int lane, int w){
    float s, c;
    sincospif((float)n0*(1.f/1024.f), &s, &c);
    twb = make_float2(c, -s);
    sincospif((float)(w*br5(lane))*(1.f/128.f), &s, &c);
    tw2 = make_float2(c, -s);
}

// ---------------------------------------------------------------------------
// Merged precompute + combine: 2 blocks; block j computes its 4 spectra
// sequentially, then builds g_HH/g_A/g_B for pair j. (2 launches total/call.)
// ---------------------------------------------------------------------------
__global__ void __launch_bounds__(NT)
prep_kernel(const float* __restrict__ G, const float* __restrict__ H)
{
    __shared__ float2 sm2[2112];
    float* smf = (float*)sm2;
    int tid = threadIdx.x, lane = tid & 31, w = tid >> 5;
    int n0 = w + 8*lane;
    int jp = blockIdx.x;
    LaneTw T = make_lane_tw(lane);
    float2 twb, tw2;
    setup_tw(twb, tw2, n0, lane, w);

#pragma unroll 1
    for (int wb = 0; wb < 4; wb++){
        const float* src = (wb < 2) ? (G + (2*jp + wb)*NN) : (H + (2*jp + wb - 2)*NN);
        for (int idx = tid; idx < NN; idx += NT) smf[idx + (idx>>5)] = src[idx];
        __syncthreads();

        float2 xt[8];
        if (wb < 2){
#pragma unroll
            for (int t = 0; t < 8; t++){
                int n = n0 + 256*t;
                xt[t] = make_float2(smf[n + (n>>5)], 0.f);
            }
        } else {
#pragma unroll
            for (int t = 0; t < 8; t++){
                int n = n0 + 256*t;
                int j = (NN - n) & (NN - 1);
                float hv = smf[j + (j>>5)];
                float s, c; sincospif((float)j*(1.f/(float)NN), &s, &c);
                xt[t] = make_float2(hv*c, hv*s);
            }
        }
        __syncthreads();

        float2 xh[8];
        fwd2048(xt, xh, sm2, twb, tw2, T, lane, w);

        float2* dst = (wb < 2) ? g_Ghat[2*jp + wb] : g_Hhat[2*jp + wb - 2];
#pragma unroll
        for (int v = 0; v < 8; v++) dst[256*v + 32*w + lane] = xh[v];
        __syncthreads();
    }

    const float cs = 0.5f / (float)NN;
    for (int k = tid; k < NN; k += NT){
        float2 g0 = g_Ghat[2*jp][k], g1 = g_Ghat[2*jp+1][k];
        float2 h0 = g_Hhat[2*jp][k], h1 = g_Hhat[2*jp+1][k];
        g_A[jp][k]  = make_float2((g0.x + g1.y) * cs, (g0.y - g1.x) * cs);
        g_B[jp][k]  = make_float2((g0.x - g1.y) * cs, (g0.y + g1.x) * cs);
        g_HH[jp][k] = make_float2(h0.x - h1.y,        h0.y + h1.x);
    }
}

// ---------------------------------------------------------------------------
// Main: TWO rows per CTA, 3 CTAs/SM.
// dyn smem: sm2[2112] | Xa[2048] | Xb[2048] = 48.5KB
// ---------------------------------------------------------------------------
__global__ void __launch_bounds__(NT, 3)
toeplitz_kernel(const float* __restrict__ x, float* __restrict__ out)
{
    extern __shared__ float2 smx[];
    float2* sm2  = smx;
    float2* Xa_s = smx + 2112;
    float2* Xb_s = smx + 4160;
    float* smfA = (float*)Xa_s;
    float* smfB = (float*)Xb_s;

    int tid = threadIdx.x, lane = tid & 31, w = tid >> 5;
    int n0 = w + 8*lane;
    LaneTw T = make_lane_tw(lane);
    float2 twb, tw2;
    setup_tw(twb, tw2, n0, lane, w);
    float2 etaC0;
    { float s, c; sincospif((float)n0*(1.f/(float)NN), &s, &c); etaC0 = make_float2(c, -s); }
    const float2 STEPC = make_float2(0.92387953251128674f, -0.38268343236508977f); // e^{-i pi/8}
    const float2 STEPP = make_float2(0.92387953251128674f,  0.38268343236508977f); // e^{+i pi/8}

    size_t row = (size_t)blockIdx.x * 2;
    const float* xa = x + row * NN;
    const float* xb = xa + NN;

    for (int idx = tid; idx < NN; idx += NT){
        smfA[idx + (idx>>5)] = xa[idx];
        smfB[idx + (idx>>5)] = xb[idx];
    }
    __syncthreads();

    // packed z = (x_a + i x_b) * conj(eta)^n
    float2 xt[8];
    { float2 cur = etaC0;
#pragma unroll
      for (int t = 0; t < 8; t++){
          int n = n0 + 256*t;
          float va = smfA[n + (n>>5)];
          float vb = smfB[n + (n>>5)];
          xt[t] = cmul(make_float2(va, vb), cur);
          cur = cmul(cur, STEPC);
      } }

    float2 zh[8];
    fwd2048(xt, zh, sm2, twb, tw2, T, lane, w);   // leading sync drains smf reads

    // store Zhat by frequency digits (same cells this thread just read: no sync)
#pragma unroll
    for (int v = 0; v < 8; v++) sm2[(v*8 + w)*33 + lane] = zh[v];
    __syncthreads();

    // split: Ma = (Z + conj(Z[2047-k]))/2 ; Mb = (Z - conj(Z[2047-k]))/2i
#pragma unroll
    for (int v = 0; v < 8; v++){
        int k  = 256*v + 8*lane + w;
        int kn = 2047 - k;
        float2 zn = sm2[((kn>>8)*8 + (kn&7))*33 + ((kn>>3)&31)];
        zn.y = -zn.y;                                  // conj
        float2 Ma = make_float2(0.5f*(zh[v].x + zn.x), 0.5f*(zh[v].y + zn.y));
        float2 D  = csub(zh[v], zn);
        float2 Mb = make_float2(0.5f*D.y, -0.5f*D.x);  // D / (2i)
        int fidx = 256*v + 32*w + lane;
        Xa_s[fidx] = Ma;
        Xb_s[fidx] = Mb;
    }
    __syncthreads();

    // P accumulates Yhat_a + i*Yhat_b directly (single 8-reg accumulator)
    float2 P[8];
#pragma unroll
    for (int v = 0; v < 8; v++) P[v] = make_float2(0.f, 0.f);

#pragma unroll
    for (int rs = 0; rs < 2; rs++){
        const float2* __restrict__ Xs = rs ? Xb_s : Xa_s;
#pragma unroll 1
        for (int jj = 0; jj < 2; jj++){
            const float2* __restrict__ HH = g_HH[jj];
            const float2* __restrict__ A  = g_A[jj];
            const float2* __restrict__ B  = g_B[jj];

            float2 q[8];
#pragma unroll
            for (int v = 0; v < 8; v++){
                int fidx = 256*v + 32*w + lane;
                q[v] = cmul(HH[fidx], Xs[fidx]);
            }

            float2 zt[8];
            inv2048(q, zt, sm2, twb, tw2, T, lane, w);

            { float2 cur = make_float2(etaC0.x, -etaC0.y);   // eta^n chain
#pragma unroll
              for (int t = 0; t < 8; t++){
                  zt[t] = cmul(cur, zt[t]);
                  cur = cmul(cur, STEPP);
              } }

            float2 Wv[8];
            fwd2048(zt, Wv, sm2, twb, tw2, T, lane, w);

            __syncthreads();
#pragma unroll
            for (int v = 0; v < 8; v++)
                sm2[(v*8 + w)*33 + lane] = Wv[v];
            __syncthreads();
#pragma unroll
            for (int v = 0; v < 8; v++){
                int k  = 256*v + 8*lane + w;
                int kn = (NN - k) & (NN - 1);
                float2 wp = sm2[((kn>>8)*8 + (kn&7))*33 + ((kn>>3)&31)];
                int fidx = 256*v + 32*w + lane;
                float2 acc = cadd(cmul(A[fidx], Wv[v]), cmulj(B[fidx], wp));
                if (rs == 0) P[v] = cadd(P[v], acc);
                else         P[v] = cadd(P[v], make_float2(-acc.y, acc.x));  // + i*acc
            }
        }
    }

    float2 rt[8];
    inv2048(P, rt, sm2, twb, tw2, T, lane, w);

    __syncthreads();
#pragma unroll
    for (int t = 0; t < 8; t++){
        int n = n0 + 256*t;
        smfA[n + (n>>5)] = rt[t].x * (1.f/(float)NN);
        smfB[n + (n>>5)] = rt[t].y * (1.f/(float)NN);
    }
    __syncthreads();

    float* oa = out + row * NN;
    float* ob = oa + NN;
    for (int idx = tid; idx < NN; idx += NT){
        oa[idx] = smfA[idx + (idx>>5)];
        ob[idx] = smfB[idx + (idx>>5)];
    }
}

// ---------------------------------------------------------------------------
extern "C" void kernel_launch(void* const* d_in, const int* in_sizes, int n_in,
                              void* d_out, int out_size)
{
    const float* x = (const float*)d_in[0];
    const float* G = (const float*)d_in[1];
    const float* H = (const float*)d_in[2];
    float* out = (float*)d_out;
    (void)in_sizes; (void)n_in; (void)out_size;

    size_t smem = (size_t)(2112 + 2048 + 2048) * sizeof(float2);   // 49,664 B
    cudaFuncSetAttribute(toeplitz_kernel,
                         cudaFuncAttributeMaxDynamicSharedMemorySize, (int)smem);

    prep_kernel<<<2, NT>>>(G, H);
    toeplitz_kernel<<<2048, NT, smem>>>(x, out);
}

// round 12
// speedup vs baseline: 1.1405x; 1.1405x over previous
#include <cuda_runtime.h>
#include <cuda_bf16.h>

#define NN 2048
#define RR 4
#define NT 256
#define BR3(j) ((((j)&1)<<2) | ((j)&2) | (((j)&4)>>2))

// Filters, storage index fidx = 256v + 32s + c  (frequency k = 256v + 8c + s)
__device__ float2 g_Ghat[RR][NN];
__device__ float2 g_Hhat[RR][NN];
__device__ float2 g_HH[2][NN];
__device__ float2 g_A [2][NN];
__device__ float2 g_B [2][NN];

__device__ __forceinline__ float2 cadd(float2 a, float2 b){ return make_float2(a.x+b.x, a.y+b.y); }
__device__ __forceinline__ float2 csub(float2 a, float2 b){ return make_float2(a.x-b.x, a.y-b.y); }
__device__ __forceinline__ float2 cmul(float2 a, float2 b){
    return make_float2(a.x*b.x - a.y*b.y, a.x*b.y + a.y*b.x);
}
__device__ __forceinline__ float2 cmulj(float2 a, float2 b){   // a * conj(b)
    return make_float2(a.x*b.x + a.y*b.y, a.y*b.x - a.x*b.y);
}
__device__ __forceinline__ float2 csqr(float2 a){ return make_float2(a.x*a.x - a.y*a.y, 2.f*a.x*a.y); }
__device__ __forceinline__ int br5(int x){ return (int)(__brev((unsigned)x) >> 27); }

__device__ __forceinline__ float2 shfl_xor_c(float2 v, int m){
    return make_float2(__shfl_xor_sync(0xffffffffu, v.x, m),
                       __shfl_xor_sync(0xffffffffu, v.y, m));
}
__device__ __forceinline__ float2 bfly(float2 p, float2 v, float s){
    return make_float2(fmaf(s, v.x, p.x), fmaf(s, v.y, p.y));
}

struct LaneTw {
    float2 W16, W8, W4;
    float s16, s8, s4, s2, s1;
};

__device__ __forceinline__ LaneTw make_lane_tw(int lane){
    float s, c;
    sincospif((float)(lane & 15) * (1.f/16.f), &s, &c);
    float2 w16 = make_float2(c, -s);
    float2 w8 = csqr(w16); if (lane & 8){ w8.x = -w8.x; w8.y = -w8.y; }
    float2 w4 = csqr(w8);  if (lane & 4){ w4.x = -w4.x; w4.y = -w4.y; }
    LaneTw T;
    T.W16 = (lane & 16) ? w16 : make_float2(1.f, 0.f);
    T.W8  = (lane & 8)  ? w8  : make_float2(1.f, 0.f);
    T.W4  = (lane & 4)  ? w4  : make_float2(1.f, 0.f);
    T.s16 = (lane & 16) ? -1.f : 1.f;
    T.s8  = (lane & 8)  ? -1.f : 1.f;
    T.s4  = (lane & 4)  ? -1.f : 1.f;
    T.s2  = (lane & 2)  ? -1.f : 1.f;
    T.s1  = (lane & 1)  ? -1.f : 1.f;
    return T;
}

__device__ __forceinline__ float2 fft32_fwd(float2 v, const LaneTw& T, int lane){
    float2 p, t;
    p = shfl_xor_c(v, 16);
    t = bfly(p, v, T.s16);  v = cmul(t, T.W16);
    p = shfl_xor_c(v, 8);
    t = bfly(p, v, T.s8);   v = cmul(t, T.W8);
    p = shfl_xor_c(v, 4);
    t = bfly(p, v, T.s4);   v = cmul(t, T.W4);
    p = shfl_xor_c(v, 2);
    t = bfly(p, v, T.s2);
    v = ((lane & 3) == 3) ? make_float2(t.y, -t.x) : t;
    p = shfl_xor_c(v, 1);
    v = bfly(p, v, T.s1);
    return v;
}

__device__ __forceinline__ float2 fft32_inv(float2 v, const LaneTw& T, int lane){
    float2 p;
    p = shfl_xor_c(v, 1);
    v = bfly(p, v, T.s1);
    if ((lane & 3) == 3) v = make_float2(-v.y, v.x);
    p = shfl_xor_c(v, 2);
    v = bfly(p, v, T.s2);
    v = cmulj(v, T.W4);
    p = shfl_xor_c(v, 4);
    v = bfly(p, v, T.s4);
    v = cmulj(v, T.W8);
    p = shfl_xor_c(v, 8);
    v = bfly(p, v, T.s8);
    v = cmulj(v, T.W16);
    p = shfl_xor_c(v, 16);
    v = bfly(p, v, T.s16);
    return v;
}

__device__ __forceinline__ void fft8_fwd(float2 r[8]){
    const float R2 = 0.70710678118654752440f;
    float2 a, d;
    a = r[0]; r[0] = cadd(a, r[4]); r[4] = csub(a, r[4]);
    a = r[1]; d = csub(a, r[5]); r[1] = cadd(a, r[5]);
              r[5] = make_float2((d.x + d.y)*R2, (d.y - d.x)*R2);
    a = r[2]; d = csub(a, r[6]); r[2] = cadd(a, r[6]);
              r[6] = make_float2(d.y, -d.x);
    a = r[3]; d = csub(a, r[7]); r[3] = cadd(a, r[7]);
              r[7] = make_float2((d.y - d.x)*R2, -(d.x + d.y)*R2);
    a = r[0]; r[0] = cadd(a, r[2]); r[2] = csub(a, r[2]);
    a = r[1]; d = csub(a, r[3]); r[1] = cadd(a, r[3]); r[3] = make_float2(d.y, -d.x);
    a = r[4]; r[4] = cadd(a, r[6]); r[6] = csub(a, r[6]);
    a = r[5]; d = csub(a, r[7]); r[5] = cadd(a, r[7]); r[7] = make_float2(d.y, -d.x);
    a = r[0]; r[0] = cadd(a, r[1]); r[1] = csub(a, r[1]);
    a = r[2]; r[2] = cadd(a, r[3]); r[3] = csub(a, r[3]);
    a = r[4]; r[4] = cadd(a, r[5]); r[5] = csub(a, r[5]);
    a = r[6]; r[6] = cadd(a, r[7]); r[7] = csub(a, r[7]);
}

__device__ __forceinline__ void fft8_inv(float2 r[8]){
    const float R2 = 0.70710678118654752440f;
    float2 a, d;
    a = r[0]; r[0] = cadd(a, r[1]); r[1] = csub(a, r[1]);
    a = r[2]; r[2] = cadd(a, r[3]); r[3] = csub(a, r[3]);
    a = r[4]; r[4] = cadd(a, r[5]); r[5] = csub(a, r[5]);
    a = r[6]; r[6] = cadd(a, r[7]); r[7] = csub(a, r[7]);
    a = r[0]; r[0] = cadd(a, r[2]); r[2] = csub(a, r[2]);
    d = make_float2(-r[3].y, r[3].x); a = r[1]; r[1] = cadd(a, d); r[3] = csub(a, d);
    a = r[4]; r[4] = cadd(a, r[6]); r[6] = csub(a, r[6]);
    d = make_float2(-r[7].y, r[7].x); a = r[5]; r[5] = cadd(a, d); r[7] = csub(a, d);
    d = r[4];                                       a = r[0]; r[0] = cadd(a, d); r[4] = csub(a, d);
    d = make_float2((r[5].x - r[5].y)*R2, (r[5].x + r[5].y)*R2);
                                                    a = r[1]; r[1] = cadd(a, d); r[5] = csub(a, d);
    d = make_float2(-r[6].y, r[6].x);               a = r[2]; r[2] = cadd(a, d); r[6] = csub(a, d);
    d = make_float2(-(r[7].x + r[7].y)*R2, (r[7].x - r[7].y)*R2);
                                                    a = r[3]; r[3] = cadd(a, d); r[7] = csub(a, d);
}

// ------------------- single-stream transforms (pre/post phases) -------------
__device__ __forceinline__ void fwd2048(float2 xt[8], float2 xh[8], float2* sm2,
                                        float2 twb, float2 tw2,
                                        const LaneTw& T, int lane, int w)
{
    fft8_fwd(xt);
    {
        float2 cur = twb;
#pragma unroll
        for (int s = 1; s < 8; s++){
            xt[BR3(s)] = cmul(xt[BR3(s)], cur);
            if (s < 7) cur = cmul(cur, twb);
        }
    }
    int c = br5(lane);
    __syncthreads();
#pragma unroll
    for (int j = 0; j < 8; j++){
        float2 v = fft32_fwd(xt[j], T, lane);
        v = cmul(v, tw2);
        sm2[(w*8 + BR3(j))*33 + c] = v;
    }
    __syncthreads();
    float2 m[8];
#pragma unroll
    for (int rr = 0; rr < 8; rr++) m[rr] = sm2[(rr*8 + w)*33 + lane];
    fft8_fwd(m);
#pragma unroll
    for (int v = 0; v < 8; v++) xh[v] = m[BR3(v)];
}

__device__ __forceinline__ void inv2048(float2 q[8], float2 xt[8], float2* sm2,
                                        float2 twb, float2 tw2,
                                        const LaneTw& T, int lane, int w)
{
    float2 r[8];
#pragma unroll
    for (int j = 0; j < 8; j++) r[j] = q[BR3(j)];
    fft8_inv(r);
    __syncthreads();
#pragma unroll
    for (int rr = 0; rr < 8; rr++) sm2[(rr*8 + w)*33 + lane] = r[rr];
    __syncthreads();
    int c = br5(lane);
    float2 rs[8];
#pragma unroll
    for (int s = 0; s < 8; s++){
        float2 v = sm2[(w*8 + s)*33 + c];
        v = cmulj(v, tw2);
        rs[s] = fft32_inv(v, T, lane);
    }
    xt[0] = rs[0];
    {
        float2 cur = twb;
#pragma unroll
        for (int s = 1; s < 8; s++){
            xt[BR3(s)] = cmulj(rs[s], cur);
            if (s < 7) cur = cmul(cur, twb);
        }
    }
    fft8_inv(xt);
}

// ------------------- dual-stream transforms (mainloop) ----------------------
__device__ __forceinline__ void fwd2048x2(float2 xa[8], float2 xb[8],
                                          float2 xha[8], float2 xhb[8],
                                          float2* sma, float2* smb,
                                          float2 twb, float2 tw2,
                                          const LaneTw& T, int lane, int w)
{
    fft8_fwd(xa); fft8_fwd(xb);
    {
        float2 cur = twb;
#pragma unroll
        for (int s = 1; s < 8; s++){
            xa[BR3(s)] = cmul(xa[BR3(s)], cur);
            xb[BR3(s)] = cmul(xb[BR3(s)], cur);
            if (s < 7) cur = cmul(cur, twb);
        }
    }
    int c = br5(lane);
    __syncthreads();
#pragma unroll
    for (int j = 0; j < 8; j++){
        float2 va = fft32_fwd(xa[j], T, lane);
        float2 vb = fft32_fwd(xb[j], T, lane);
        va = cmul(va, tw2);
        vb = cmul(vb, tw2);
        int ad = (w*8 + BR3(j))*33 + c;
        sma[ad] = va;
        smb[ad] = vb;
    }
    __syncthreads();
    float2 ma[8], mb[8];
#pragma unroll
    for (int rr = 0; rr < 8; rr++){
        int ad = (rr*8 + w)*33 + lane;
        ma[rr] = sma[ad];
        mb[rr] = smb[ad];
    }
    fft8_fwd(ma); fft8_fwd(mb);
#pragma unroll
    for (int v = 0; v < 8; v++){ xha[v] = ma[BR3(v)]; xhb[v] = mb[BR3(v)]; }
}

__device__ __forceinline__ void inv2048x2(float2 qa[8], float2 qb[8],
                                          float2 xta[8], float2 xtb[8],
                                          float2* sma, float2* smb,
                                          float2 twb, float2 tw2,
                                          const LaneTw& T, int lane, int w)
{
    float2 ra[8], rb[8];
#pragma unroll
    for (int j = 0; j < 8; j++){ ra[j] = qa[BR3(j)]; rb[j] = qb[BR3(j)]; }
    fft8_inv(ra); fft8_inv(rb);
    __syncthreads();
#pragma unroll
    for (int rr = 0; rr < 8; rr++){
        int ad = (rr*8 + w)*33 + lane;
        sma[ad] = ra[rr];
        smb[ad] = rb[rr];
    }
    __syncthreads();
    int c = br5(lane);
    float2 rsa[8], rsb[8];
#pragma unroll
    for (int s = 0; s < 8; s++){
        int ad = (w*8 + s)*33 + c;
        float2 va = cmulj(sma[ad], tw2);
        float2 vb = cmulj(smb[ad], tw2);
        rsa[s] = fft32_inv(va, T, lane);
        rsb[s] = fft32_inv(vb, T, lane);
    }
    xta[0] = rsa[0];
    xtb[0] = rsb[0];
    {
        float2 cur = twb;
#pragma unroll
        for (int s = 1; s < 8; s++){
            xta[BR3(s)] = cmulj(rsa[s], cur);
            xtb[BR3(s)] = cmulj(rsb[s], cur);
            if (s < 7) cur = cmul(cur, twb);
        }
    }
    fft8_inv(xta); fft8_inv(xtb);
}

__device__ __forceinline__ void setup_tw(float2& twb, float2& tw2, int n0, int lane, int w){
    float s, c;
    sincospif((float)n0*(1.f/1024.f), &s, &c);
    twb = make_float2(c, -s);
    sincospif((float)(w*br5(lane))*(1.f/128.f), &s, &c);
    tw2 = make_float2(c, -s);
}

// ---------------------------------------------------------------------------
// Merged precompute + combine (2 launches total per call).
// ---------------------------------------------------------------------------
__global__ void __launch_bounds__(NT)
prep_kernel(const float* __restrict__ G, const float* __restrict__ H)
{
    __shared__ float2 sm2[2112];
    float* smf = (float*)sm2;
    int tid = threadIdx.x, lane = tid & 31, w = tid >> 5;
    int n0 = w + 8*lane;
    int jp = blockIdx.x;
    LaneTw T = make_lane_tw(lane);
    float2 twb, tw2;
    setup_tw(twb, tw2, n0, lane, w);

#pragma unroll 1
    for (int wb = 0; wb < 4; wb++){
        const float* src = (wb < 2) ? (G + (2*jp + wb)*NN) : (H + (2*jp + wb - 2)*NN);
        for (int idx = tid; idx < NN; idx += NT) smf[idx + (idx>>5)] = src[idx];
        __syncthreads();

        float2 xt[8];
        if (wb < 2){
#pragma unroll
            for (int t = 0; t < 8; t++){
                int n = n0 + 256*t;
                xt[t] = make_float2(smf[n + (n>>5)], 0.f);
            }
        } else {
#pragma unroll
            for (int t = 0; t < 8; t++){
                int n = n0 + 256*t;
                int j = (NN - n) & (NN - 1);
                float hv = smf[j + (j>>5)];
                float s, c; sincospif((float)j*(1.f/(float)NN), &s, &c);
                xt[t] = make_float2(hv*c, hv*s);
            }
        }
        __syncthreads();

        float2 xh[8];
        fwd2048(xt, xh, sm2, twb, tw2, T, lane, w);

        float2* dst = (wb < 2) ? g_Ghat[2*jp + wb] : g_Hhat[2*jp + wb - 2];
#pragma unroll
        for (int v = 0; v < 8; v++) dst[256*v + 32*w + lane] = xh[v];
        __syncthreads();
    }

    const float cs = 0.5f / (float)NN;
    for (int k = tid; k < NN; k += NT){
        float2 g0 = g_Ghat[2*jp][k], g1 = g_Ghat[2*jp+1][k];
        float2 h0 = g_Hhat[2*jp][k], h1 = g_Hhat[2*jp+1][k];
        g_A[jp][k]  = make_float2((g0.x + g1.y) * cs, (g0.y - g1.x) * cs);
        g_B[jp][k]  = make_float2((g0.x - g1.y) * cs, (g0.y + g1.x) * cs);
        g_HH[jp][k] = make_float2(h0.x - h1.y,        h0.y + h1.x);
    }
}

// ---------------------------------------------------------------------------
// Main: TWO rows per CTA, dual-stream interleaved mainloop.
// dyn smem: sma[2112] | smb[2112] | Xa[2048] | Xb[2048] = 66,560 B
// ---------------------------------------------------------------------------
__global__ void __launch_bounds__(NT, 2)
toeplitz_kernel(const float* __restrict__ x, float* __restrict__ out)
{
    extern __shared__ float2 smx[];
    float2* sma  = smx;
    float2* smb  = smx + 2112;
    float2* Xa_s = smx + 4224;
    float2* Xb_s = smx + 6272;
    float* smfA = (float*)Xa_s;
    float* smfB = (float*)Xb_s;

    int tid = threadIdx.x, lane = tid & 31, w = tid >> 5;
    int n0 = w + 8*lane;
    LaneTw T = make_lane_tw(lane);
    float2 twb, tw2;
    setup_tw(twb, tw2, n0, lane, w);
    float2 etaC0;
    { float s, c; sincospif((float)n0*(1.f/(float)NN), &s, &c); etaC0 = make_float2(c, -s); }
    const float2 STEPC = make_float2(0.92387953251128674f, -0.38268343236508977f); // e^{-i pi/8}
    const float2 STEPP = make_float2(0.92387953251128674f,  0.38268343236508977f); // e^{+i pi/8}

    size_t row = (size_t)blockIdx.x * 2;
    const float* xa = x + row * NN;
    const float* xb = xa + NN;

    for (int idx = tid; idx < NN; idx += NT){
        smfA[idx + (idx>>5)] = xa[idx];
        smfB[idx + (idx>>5)] = xb[idx];
    }
    __syncthreads();

    // packed z = (x_a + i x_b) * conj(eta)^n
    float2 xt[8];
    { float2 cur = etaC0;
#pragma unroll
      for (int t = 0; t < 8; t++){
          int n = n0 + 256*t;
          float va = smfA[n + (n>>5)];
          float vb = smfB[n + (n>>5)];
          xt[t] = cmul(make_float2(va, vb), cur);
          cur = cmul(cur, STEPC);
      } }

    float2 zh[8];
    fwd2048(xt, zh, sma, twb, tw2, T, lane, w);   // leading sync drains smf reads

    // store Zhat by frequency digits (same cells this thread just read: no sync)
#pragma unroll
    for (int v = 0; v < 8; v++) sma[(v*8 + w)*33 + lane] = zh[v];
    __syncthreads();

    // split: Ma = (Z + conj(Z[2047-k]))/2 ; Mb = (Z - conj(Z[2047-k]))/2i
#pragma unroll
    for (int v = 0; v < 8; v++){
        int k  = 256*v + 8*lane + w;
        int kn = 2047 - k;
        float2 zn = sma[((kn>>8)*8 + (kn&7))*33 + ((kn>>3)&31)];
        zn.y = -zn.y;                                  // conj
        float2 Ma = make_float2(0.5f*(zh[v].x + zn.x), 0.5f*(zh[v].y + zn.y));
        float2 D  = csub(zh[v], zn);
        float2 Mb = make_float2(0.5f*D.y, -0.5f*D.x);  // D / (2i)
        int fidx = 256*v + 32*w + lane;
        Xa_s[fidx] = Ma;
        Xb_s[fidx] = Mb;
    }
    __syncthreads();

    // P accumulates Yhat_a + i*Yhat_b (single 8-reg accumulator)
    float2 P[8];
#pragma unroll
    for (int v = 0; v < 8; v++) P[v] = make_float2(0.f, 0.f);

#pragma unroll 1
    for (int jj = 0; jj < 2; jj++){
        const float2* __restrict__ HH = g_HH[jj];
        const float2* __restrict__ A  = g_A[jj];
        const float2* __restrict__ B  = g_B[jj];

        float2 qa[8], qb[8];
#pragma unroll
        for (int v = 0; v < 8; v++){
            int fidx = 256*v + 32*w + lane;
            float2 h = HH[fidx];
            qa[v] = cmul(h, Xa_s[fidx]);
            qb[v] = cmul(h, Xb_s[fidx]);
        }

        float2 za[8], zb[8];
        inv2048x2(qa, qb, za, zb, sma, smb, twb, tw2, T, lane, w);

        { float2 cur = make_float2(etaC0.x, -etaC0.y);   // eta^n chain (shared)
#pragma unroll
          for (int t = 0; t < 8; t++){
              za[t] = cmul(cur, za[t]);
              zb[t] = cmul(cur, zb[t]);
              cur = cmul(cur, STEPP);
          } }

        float2 Wa[8], Wb[8];
        fwd2048x2(za, zb, Wa, Wb, sma, smb, twb, tw2, T, lane, w);

        // store W spectra by frequency digits (cells this thread just read: no sync)
#pragma unroll
        for (int v = 0; v < 8; v++){
            int ad = (v*8 + w)*33 + lane;
            sma[ad] = Wa[v];
            smb[ad] = Wb[v];
        }
        __syncthreads();
#pragma unroll
        for (int v = 0; v < 8; v++){
            int k  = 256*v + 8*lane + w;
            int kn = (NN - k) & (NN - 1);
            int ap = ((kn>>8)*8 + (kn&7))*33 + ((kn>>3)&31);
            float2 wpa = sma[ap];
            float2 wpb = smb[ap];
            int fidx = 256*v + 32*w + lane;
            float2 Av = A[fidx], Bv = B[fidx];
            float2 accA = cadd(cmul(Av, Wa[v]), cmulj(Bv, wpa));
            float2 accB = cadd(cmul(Av, Wb[v]), cmulj(Bv, wpb));
            // P += accA + i*accB
            P[v] = cadd(P[v], make_float2(accA.x - accB.y, accA.y + accB.x));
        }
    }

    float2 rt[8];
    inv2048(P, rt, sma, twb, tw2, T, lane, w);   // entry sync drains gather reads

    __syncthreads();
#pragma unroll
    for (int t = 0; t < 8; t++){
        int n = n0 + 256*t;
        smfA[n + (n>>5)] = rt[t].x * (1.f/(float)NN);
        smfB[n + (n>>5)] = rt[t].y * (1.f/(float)NN);
    }
    __syncthreads();

    float* oa = out + row * NN;
    float* ob = oa + NN;
    for (int idx = tid; idx < NN; idx += NT){
        oa[idx] = smfA[idx + (idx>>5)];
        ob[idx] = smfB[idx + (idx>>5)];
    }
}

// ---------------------------------------------------------------------------
extern "C" void kernel_launch(void* const* d_in, const int* in_sizes, int n_in,
                              void* d_out, int out_size)
{
    const float* x = (const float*)d_in[0];
    const float* G = (const float*)d_in[1];
    const float* H = (const float*)d_in[2];
    float* out = (float*)d_out;
    (void)in_sizes; (void)n_in; (void)out_size;

    size_t smem = (size_t)(2112 + 2112 + 2048 + 2048) * sizeof(float2);   // 66,560 B
    cudaFuncSetAttribute(toeplitz_kernel,
                         cudaFuncAttributeMaxDynamicSharedMemorySize, (int)smem);

    prep_kernel<<<2, NT>>>(G, H);
    toeplitz_kernel<<<2048, NT, smem>>>(x, out);
}

// round 13
// speedup vs baseline: 1.1696x; 1.0255x over previous
#include <cuda_runtime.h>
#include <cuda_bf16.h>

#define NN 2048
#define RR 4
#define NT 256
#define BR3(j) ((((j)&1)<<2) | ((j)&2) | (((j)&4)>>2))

// Filters, storage index fidx = 256v + 32s + c  (frequency k = 256v + 8c + s)
__device__ float2 g_Ghat[RR][NN];
__device__ float2 g_Hhat[RR][NN];
__device__ float2 g_HH[2][NN];
__device__ float2 g_A [2][NN];
__device__ float2 g_B [2][NN];

__device__ __forceinline__ float2 cadd(float2 a, float2 b){ return make_float2(a.x+b.x, a.y+b.y); }
__device__ __forceinline__ float2 csub(float2 a, float2 b){ return make_float2(a.x-b.x, a.y-b.y); }
__device__ __forceinline__ float2 cmul(float2 a, float2 b){
    return make_float2(a.x*b.x - a.y*b.y, a.x*b.y + a.y*b.x);
}
__device__ __forceinline__ float2 cmulj(float2 a, float2 b){   // a * conj(b)
    return make_float2(a.x*b.x + a.y*b.y, a.y*b.x - a.x*b.y);
}
__device__ __forceinline__ float2 csqr(float2 a){ return make_float2(a.x*a.x - a.y*a.y, 2.f*a.x*a.y); }
__device__ __forceinline__ int br5(int x){ return (int)(__brev((unsigned)x) >> 27); }

__device__ __forceinline__ float2 shfl_xor_c(float2 v, int m){
    return make_float2(__shfl_xor_sync(0xffffffffu, v.x, m),
                       __shfl_xor_sync(0xffffffffu, v.y, m));
}
__device__ __forceinline__ float2 bfly(float2 p, float2 v, float s){
    return make_float2(fmaf(s, v.x, p.x), fmaf(s, v.y, p.y));
}

struct LaneTw {
    float2 W16, W8, W4;
    float s16, s8, s4, s2, s1;
};

__device__ __forceinline__ LaneTw make_lane_tw(int lane){
    float s, c;
    sincospif((float)(lane & 15) * (1.f/16.f), &s, &c);
    float2 w16 = make_float2(c, -s);
    float2 w8 = csqr(w16); if (lane & 8){ w8.x = -w8.x; w8.y = -w8.y; }
    float2 w4 = csqr(w8);  if (lane & 4){ w4.x = -w4.x; w4.y = -w4.y; }
    LaneTw T;
    T.W16 = (lane & 16) ? w16 : make_float2(1.f, 0.f);
    T.W8  = (lane & 8)  ? w8  : make_float2(1.f, 0.f);
    T.W4  = (lane & 4)  ? w4  : make_float2(1.f, 0.f);
    T.s16 = (lane & 16) ? -1.f : 1.f;
    T.s8  = (lane & 8)  ? -1.f : 1.f;
    T.s4  = (lane & 4)  ? -1.f : 1.f;
    T.s2  = (lane & 2)  ? -1.f : 1.f;
    T.s1  = (lane & 1)  ? -1.f : 1.f;
    return T;
}

__device__ __forceinline__ float2 fft32_fwd(float2 v, const LaneTw& T, int lane){
    float2 p, t;
    p = shfl_xor_c(v, 16);
    t = bfly(p, v, T.s16);  v = cmul(t, T.W16);
    p = shfl_xor_c(v, 8);
    t = bfly(p, v, T.s8);   v = cmul(t, T.W8);
    p = shfl_xor_c(v, 4);
    t = bfly(p, v, T.s4);   v = cmul(t, T.W4);
    p = shfl_xor_c(v, 2);
    t = bfly(p, v, T.s2);
    v = ((lane & 3) == 3) ? make_float2(t.y, -t.x) : t;
    p = shfl_xor_c(v, 1);
    v = bfly(p, v, T.s1);
    return v;
}

__device__ __forceinline__ float2 fft32_inv(float2 v, const LaneTw& T, int lane){
    float2 p;
    p = shfl_xor_c(v, 1);
    v = bfly(p, v, T.s1);
    if ((lane & 3) == 3) v = make_float2(-v.y, v.x);
    p = shfl_xor_c(v, 2);
    v = bfly(p, v, T.s2);
    v = cmulj(v, T.W4);
    p = shfl_xor_c(v, 4);
    v = bfly(p, v, T.s4);
    v = cmulj(v, T.W8);
    p = shfl_xor_c(v, 8);
    v = bfly(p, v, T.s8);
    v = cmulj(v, T.W16);
    p = shfl_xor_c(v, 16);
    v = bfly(p, v, T.s16);
    return v;
}

__device__ __forceinline__ void fft8_fwd(float2 r[8]){
    const float R2 = 0.70710678118654752440f;
    float2 a, d;
    a = r[0]; r[0] = cadd(a, r[4]); r[4] = csub(a, r[4]);
    a = r[1]; d = csub(a, r[5]); r[1] = cadd(a, r[5]);
              r[5] = make_float2((d.x + d.y)*R2, (d.y - d.x)*R2);
    a = r[2]; d = csub(a, r[6]); r[2] = cadd(a, r[6]);
              r[6] = make_float2(d.y, -d.x);
    a = r[3]; d = csub(a, r[7]); r[3] = cadd(a, r[7]);
              r[7] = make_float2((d.y - d.x)*R2, -(d.x + d.y)*R2);
    a = r[0]; r[0] = cadd(a, r[2]); r[2] = csub(a, r[2]);
    a = r[1]; d = csub(a, r[3]); r[1] = cadd(a, r[3]); r[3] = make_float2(d.y, -d.x);
    a = r[4]; r[4] = cadd(a, r[6]); r[6] = csub(a, r[6]);
    a = r[5]; d = csub(a, r[7]); r[5] = cadd(a, r[7]); r[7] = make_float2(d.y, -d.x);
    a = r[0]; r[0] = cadd(a, r[1]); r[1] = csub(a, r[1]);
    a = r[2]; r[2] = cadd(a, r[3]); r[3] = csub(a, r[3]);
    a = r[4]; r[4] = cadd(a, r[5]); r[5] = csub(a, r[5]);
    a = r[6]; r[6] = cadd(a, r[7]); r[7] = csub(a, r[7]);
}

__device__ __forceinline__ void fft8_inv(float2 r[8]){
    const float R2 = 0.70710678118654752440f;
    float2 a, d;
    a = r[0]; r[0] = cadd(a, r[1]); r[1] = csub(a, r[1]);
    a = r[2]; r[2] = cadd(a, r[3]); r[3] = csub(a, r[3]);
    a = r[4]; r[4] = cadd(a, r[5]); r[5] = csub(a, r[5]);
    a = r[6]; r[6] = cadd(a, r[7]); r[7] = csub(a, r[7]);
    a = r[0]; r[0] = cadd(a, r[2]); r[2] = csub(a, r[2]);
    d = make_float2(-r[3].y, r[3].x); a = r[1]; r[1] = cadd(a, d); r[3] = csub(a, d);
    a = r[4]; r[4] = cadd(a, r[6]); r[6] = csub(a, r[6]);
    d = make_float2(-r[7].y, r[7].x); a = r[5]; r[5] = cadd(a, d); r[7] = csub(a, d);
    d = r[4];                                       a = r[0]; r[0] = cadd(a, d); r[4] = csub(a, d);
    d = make_float2((r[5].x - r[5].y)*R2, (r[5].x + r[5].y)*R2);
                                                    a = r[1]; r[1] = cadd(a, d); r[5] = csub(a, d);
    d = make_float2(-r[6].y, r[6].x);               a = r[2]; r[2] = cadd(a, d); r[6] = csub(a, d);
    d = make_float2(-(r[7].x + r[7].y)*R2, (r[7].x - r[7].y)*R2);
                                                    a = r[3]; r[3] = cadd(a, d); r[7] = csub(a, d);
}

// BR3 is an involution: in-place permute = two register swaps.
__device__ __forceinline__ void swap_br3(float2 r[8]){
    float2 t = r[1]; r[1] = r[4]; r[4] = t;
    t = r[3]; r[3] = r[6]; r[6] = t;
}

// ------------------- single-stream transforms (pre/post phases) -------------
__device__ __forceinline__ void fwd2048(float2 xt[8], float2 xh[8], float2* sm2,
                                        float2 twb, float2 tw2,
                                        const LaneTw& T, int lane, int w)
{
    fft8_fwd(xt);
    {
        float2 cur = twb;
#pragma unroll
        for (int s = 1; s < 8; s++){
            xt[BR3(s)] = cmul(xt[BR3(s)], cur);
            if (s < 7) cur = cmul(cur, twb);
        }
    }
    int c = br5(lane);
    __syncthreads();
#pragma unroll
    for (int j = 0; j < 8; j++){
        float2 v = fft32_fwd(xt[j], T, lane);
        v = cmul(v, tw2);
        sm2[(w*8 + BR3(j))*33 + c] = v;
    }
    __syncthreads();
    float2 m[8];
#pragma unroll
    for (int rr = 0; rr < 8; rr++) m[rr] = sm2[(rr*8 + w)*33 + lane];
    fft8_fwd(m);
#pragma unroll
    for (int v = 0; v < 8; v++) xh[v] = m[BR3(v)];
}

__device__ __forceinline__ void inv2048(float2 q[8], float2 xt[8], float2* sm2,
                                        float2 twb, float2 tw2,
                                        const LaneTw& T, int lane, int w)
{
    float2 r[8];
#pragma unroll
    for (int j = 0; j < 8; j++) r[j] = q[BR3(j)];
    fft8_inv(r);
    __syncthreads();
#pragma unroll
    for (int rr = 0; rr < 8; rr++) sm2[(rr*8 + w)*33 + lane] = r[rr];
    __syncthreads();
    int c = br5(lane);
    float2 rs[8];
#pragma unroll
    for (int s = 0; s < 8; s++){
        float2 v = sm2[(w*8 + s)*33 + c];
        v = cmulj(v, tw2);
        rs[s] = fft32_inv(v, T, lane);
    }
    xt[0] = rs[0];
    {
        float2 cur = twb;
#pragma unroll
        for (int s = 1; s < 8; s++){
            xt[BR3(s)] = cmulj(rs[s], cur);
            if (s < 7) cur = cmul(cur, twb);
        }
    }
    fft8_inv(xt);
}

// ------------------- quad-stream transforms (mainloop, in-place) ------------
__device__ __forceinline__ void fwd2048x4(float2 x[4][8],
        float2* s0, float2* s1, float2* s2, float2* s3,
        float2 twb, float2 tw2, const LaneTw& T, int lane, int w)
{
    float2* const smv[4] = {s0, s1, s2, s3};
#pragma unroll
    for (int st = 0; st < 4; st++) fft8_fwd(x[st]);
    {
        float2 cur = twb;
#pragma unroll
        for (int s = 1; s < 8; s++){
#pragma unroll
            for (int st = 0; st < 4; st++)
                x[st][BR3(s)] = cmul(x[st][BR3(s)], cur);
            if (s < 7) cur = cmul(cur, twb);
        }
    }
    int c = br5(lane);
    __syncthreads();
#pragma unroll
    for (int j = 0; j < 8; j++){
        int ad = (w*8 + BR3(j))*33 + c;
#pragma unroll
        for (int st = 0; st < 4; st++){
            float2 v = fft32_fwd(x[st][j], T, lane);
            smv[st][ad] = cmul(v, tw2);
        }
    }
    __syncthreads();
#pragma unroll
    for (int rr = 0; rr < 8; rr++){
        int ad = (rr*8 + w)*33 + lane;
#pragma unroll
        for (int st = 0; st < 4; st++) x[st][rr] = smv[st][ad];
    }
#pragma unroll
    for (int st = 0; st < 4; st++){ fft8_fwd(x[st]); swap_br3(x[st]); }
    // x[st][v] now holds frequency k = 256v + 8*lane + w
}

__device__ __forceinline__ void inv2048x4(float2 q[4][8],
        float2* s0, float2* s1, float2* s2, float2* s3,
        float2 twb, float2 tw2, const LaneTw& T, int lane, int w)
{
    float2* const smv[4] = {s0, s1, s2, s3};
#pragma unroll
    for (int st = 0; st < 4; st++){ swap_br3(q[st]); fft8_inv(q[st]); }
    __syncthreads();
#pragma unroll
    for (int rr = 0; rr < 8; rr++){
        int ad = (rr*8 + w)*33 + lane;
#pragma unroll
        for (int st = 0; st < 4; st++) smv[st][ad] = q[st][rr];
    }
    __syncthreads();
    int c = br5(lane);
#pragma unroll
    for (int s = 0; s < 8; s++){
        int ad = (w*8 + s)*33 + c;
#pragma unroll
        for (int st = 0; st < 4; st++){
            float2 v = cmulj(smv[st][ad], tw2);
            q[st][s] = fft32_inv(v, T, lane);
        }
    }
    {
        float2 cur = twb;
#pragma unroll
        for (int s = 1; s < 8; s++){
#pragma unroll
            for (int st = 0; st < 4; st++)
                q[st][s] = cmulj(q[st][s], cur);
            if (s < 7) cur = cmul(cur, twb);
        }
    }
#pragma unroll
    for (int st = 0; st < 4; st++){ swap_br3(q[st]); fft8_inv(q[st]); }
    // q[st][t] now time-domain (unscaled x2048)
}

__device__ __forceinline__ void setup_tw(float2& twb, float2& tw2, int n0, int lane, int w){
    float s, c;
    sincospif((float)n0*(1.f/1024.f), &s, &c);
    twb = make_float2(c, -s);
    sincospif((float)(w*br5(lane))*(1.f/128.f), &s, &c);
    tw2 = make_float2(c, -s);
}

// ---------------------------------------------------------------------------
// Merged precompute + combine (2 launches total per call).
// ---------------------------------------------------------------------------
__global__ void __launch_bounds__(NT)
prep_kernel(const float* __restrict__ G, const float* __restrict__ H)
{
    __shared__ float2 sm2[2112];
    float* smf = (float*)sm2;
    int tid = threadIdx.x, lane = tid & 31, w = tid >> 5;
    int n0 = w + 8*lane;
    int jp = blockIdx.x;
    LaneTw T = make_lane_tw(lane);
    float2 twb, tw2;
    setup_tw(twb, tw2, n0, lane, w);

#pragma unroll 1
    for (int wb = 0; wb < 4; wb++){
        const float* src = (wb < 2) ? (G + (2*jp + wb)*NN) : (H + (2*jp + wb - 2)*NN);
        for (int idx = tid; idx < NN; idx += NT) smf[idx + (idx>>5)] = src[idx];
        __syncthreads();

        float2 xt[8];
        if (wb < 2){
#pragma unroll
            for (int t = 0; t < 8; t++){
                int n = n0 + 256*t;
                xt[t] = make_float2(smf[n + (n>>5)], 0.f);
            }
        } else {
#pragma unroll
            for (int t = 0; t < 8; t++){
                int n = n0 + 256*t;
                int j = (NN - n) & (NN - 1);
                float hv = smf[j + (j>>5)];
                float s, c; sincospif((float)j*(1.f/(float)NN), &s, &c);
                xt[t] = make_float2(hv*c, hv*s);
            }
        }
        __syncthreads();

        float2 xh[8];
        fwd2048(xt, xh, sm2, twb, tw2, T, lane, w);

        float2* dst = (wb < 2) ? g_Ghat[2*jp + wb] : g_Hhat[2*jp + wb - 2];
#pragma unroll
        for (int v = 0; v < 8; v++) dst[256*v + 32*w + lane] = xh[v];
        __syncthreads();
    }

    const float cs = 0.5f / (float)NN;
    for (int k = tid; k < NN; k += NT){
        float2 g0 = g_Ghat[2*jp][k], g1 = g_Ghat[2*jp+1][k];
        float2 h0 = g_Hhat[2*jp][k], h1 = g_Hhat[2*jp+1][k];
        g_A[jp][k]  = make_float2((g0.x + g1.y) * cs, (g0.y - g1.x) * cs);
        g_B[jp][k]  = make_float2((g0.x - g1.y) * cs, (g0.y + g1.x) * cs);
        g_HH[jp][k] = make_float2(h0.x - h1.y,        h0.y + h1.x);
    }
}

// ---------------------------------------------------------------------------
// Main: TWO rows per CTA, quad-stream (row x jj) single-pass mainloop.
// dyn smem: 4 transpose buffers of 2112 float2 = 67,584 B.
// X tiles / float staging alias buffers 2 and 3 (lifetimes disjoint).
// ---------------------------------------------------------------------------
__global__ void __launch_bounds__(NT, 2)
toeplitz_kernel(const float* __restrict__ x, float* __restrict__ out)
{
    extern __shared__ float2 smx[];
    float2* sm0 = smx;
    float2* sm1 = smx + 2112;
    float2* sm2 = smx + 4224;
    float2* sm3 = smx + 6336;

    int tid = threadIdx.x, lane = tid & 31, w = tid >> 5;
    int n0 = w + 8*lane;
    LaneTw T = make_lane_tw(lane);
    float2 twb, tw2;
    setup_tw(twb, tw2, n0, lane, w);
    float2 etaC0;
    { float s, c; sincospif((float)n0*(1.f/(float)NN), &s, &c); etaC0 = make_float2(c, -s); }
    const float2 STEPC = make_float2(0.92387953251128674f, -0.38268343236508977f); // e^{-i pi/8}
    const float2 STEPP = make_float2(0.92387953251128674f,  0.38268343236508977f); // e^{+i pi/8}

    size_t row = (size_t)blockIdx.x * 2;
    const float* xa = x + row * NN;
    const float* xb = xa + NN;

    // float staging in buffers 2/3
    float* smfA = (float*)sm2;
    float* smfB = (float*)sm3;
    for (int idx = tid; idx < NN; idx += NT){
        smfA[idx + (idx>>5)] = xa[idx];
        smfB[idx + (idx>>5)] = xb[idx];
    }
    __syncthreads();

    // packed z = (x_a + i x_b) * conj(eta)^n
    float2 xt[8];
    { float2 cur = etaC0;
#pragma unroll
      for (int t = 0; t < 8; t++){
          int n = n0 + 256*t;
          float va = smfA[n + (n>>5)];
          float vb = smfB[n + (n>>5)];
          xt[t] = cmul(make_float2(va, vb), cur);
          cur = cmul(cur, STEPC);
      } }

    float2 zh[8];
    fwd2048(xt, zh, sm0, twb, tw2, T, lane, w);   // internal syncs drain staging reads

    // store Zhat by frequency digits (cells this thread just read: no sync)
#pragma unroll
    for (int v = 0; v < 8; v++) sm0[(v*8 + w)*33 + lane] = zh[v];
    __syncthreads();

    // split: Ma = (Z + conj(Z[2047-k]))/2 ; Mb = (Z - conj(Z[2047-k]))/2i
    // write X tiles into buffers 2/3 (linear fidx indexing)
#pragma unroll
    for (int v = 0; v < 8; v++){
        int k  = 256*v + 8*lane + w;
        int kn = 2047 - k;
        float2 zn = sm0[((kn>>8)*8 + (kn&7))*33 + ((kn>>3)&31)];
        zn.y = -zn.y;                                  // conj
        float2 Ma = make_float2(0.5f*(zh[v].x + zn.x), 0.5f*(zh[v].y + zn.y));
        float2 D  = csub(zh[v], zn);
        float2 Mb = make_float2(0.5f*D.y, -0.5f*D.x);  // D / (2i)
        int fidx = 256*v + 32*w + lane;
        sm2[fidx] = Ma;
        sm3[fidx] = Mb;
    }
    __syncthreads();

    // ---- quad-stream mainloop: streams = (jj0,a),(jj0,b),(jj1,a),(jj1,b) ----
    float2 q[4][8];
#pragma unroll
    for (int v = 0; v < 8; v++){
        int fidx = 256*v + 32*w + lane;
        float2 xav = sm2[fidx], xbv = sm3[fidx];
        float2 h0 = g_HH[0][fidx], h1 = g_HH[1][fidx];
        q[0][v] = cmul(h0, xav);
        q[1][v] = cmul(h0, xbv);
        q[2][v] = cmul(h1, xav);
        q[3][v] = cmul(h1, xbv);
    }

    inv2048x4(q, sm0, sm1, sm2, sm3, twb, tw2, T, lane, w);  // internal sync drains X reads

    { float2 cur = make_float2(etaC0.x, -etaC0.y);           // eta^n chain (shared)
#pragma unroll
      for (int t = 0; t < 8; t++){
#pragma unroll
          for (int st = 0; st < 4; st++) q[st][t] = cmul(cur, q[st][t]);
          cur = cmul(cur, STEPP);
      } }

    fwd2048x4(q, sm0, sm1, sm2, sm3, twb, tw2, T, lane, w);

    // store W spectra by frequency (cells this thread just read: no sync)
#pragma unroll
    for (int v = 0; v < 8; v++){
        int ad = (v*8 + w)*33 + lane;
        sm0[ad] = q[0][v]; sm1[ad] = q[1][v];
        sm2[ad] = q[2][v]; sm3[ad] = q[3][v];
    }
    __syncthreads();

    // gather + build P = Yhat_a + i*Yhat_b in one pass (no long-lived accum)
    float2 P[8];
#pragma unroll
    for (int v = 0; v < 8; v++){
        int k  = 256*v + 8*lane + w;
        int kn = (NN - k) & (NN - 1);
        int ap = ((kn>>8)*8 + (kn&7))*33 + ((kn>>3)&31);
        float2 wp0 = sm0[ap], wp1 = sm1[ap], wp2 = sm2[ap], wp3 = sm3[ap];
        int fidx = 256*v + 32*w + lane;
        float2 A0 = g_A[0][fidx], B0 = g_B[0][fidx];
        float2 A1 = g_A[1][fidx], B1 = g_B[1][fidx];
        float2 aA = cadd(cmul(A0, q[0][v]), cmulj(B0, wp0));   // row a, jj0
        float2 aB = cadd(cmul(A0, q[1][v]), cmulj(B0, wp1));   // row b, jj0
        float2 cA = cadd(cmul(A1, q[2][v]), cmulj(B1, wp2));   // row a, jj1
        float2 cB = cadd(cmul(A1, q[3][v]), cmulj(B1, wp3));   // row b, jj1
        float2 Ya = cadd(aA, cA);
        float2 Yb = cadd(aB, cB);
        P[v] = make_float2(Ya.x - Yb.y, Ya.y + Yb.x);          // Ya + i*Yb
    }

    float2 rt[8];
    inv2048(P, rt, sm0, twb, tw2, T, lane, w);   // internal sync drains gather reads

    // epilogue staging: float buffers in sm1/sm2 (gather readers drained above)
    float* soA = (float*)sm1;
    float* soB = (float*)sm2;
    __syncthreads();
#pragma unroll
    for (int t = 0; t < 8; t++){
        int n = n0 + 256*t;
        soA[n + (n>>5)] = rt[t].x * (1.f/(float)NN);
        soB[n + (n>>5)] = rt[t].y * (1.f/(float)NN);
    }
    __syncthreads();

    float* oa = out + row * NN;
    float* ob = oa + NN;
    for (int idx = tid; idx < NN; idx += NT){
        oa[idx] = soA[idx + (idx>>5)];
        ob[idx] = soB[idx + (idx>>5)];
    }
}

// ---------------------------------------------------------------------------
extern "C" void kernel_launch(void* const* d_in, const int* in_sizes, int n_in,
                              void* d_out, int out_size)
{
    const float* x = (const float*)d_in[0];
    const float* G = (const float*)d_in[1];
    const float* H = (const float*)d_in[2];
    float* out = (float*)d_out;
    (void)in_sizes; (void)n_in; (void)out_size;

    size_t smem = (size_t)(4 * 2112) * sizeof(float2);   // 67,584 B
    cudaFuncSetAttribute(toeplitz_kernel,
                         cudaFuncAttributeMaxDynamicSharedMemorySize, (int)smem);

    prep_kernel<<<2, NT>>>(G, H);
    toeplitz_kernel<<<2048, NT, smem>>>(x, out);
}